// round 2
// baseline (speedup 1.0000x reference)
#include <cuda_runtime.h>
#include <cstdint>

// ---------------------------------------------------------------------------
// Loss_46102178955400:
//   ce    = mean NLL over train_logits [N_TRAIN, C]
//   align = sum_g sum_k ||centroid_g - member_gk|| / N_unl
//   robust= sum_g sum_{i<j} ||member_gi - member_gj|| / (K * N_unl)
//   out   = ce + 1.0*align + 0.5*robust
// Shapes: N_TRAIN=4096, C=1000, N_UNL=32768, G=512, K=64
// NOTE: index tensors are int32 (JAX demotes int64 without x64 mode).
// ---------------------------------------------------------------------------

#define LAMBDA_1 1.0f
#define LAMBDA_2 0.5f

#define KMEM   64      // members per group
#define KTILE  128     // k-chunk of the C dimension per smem tile
#define PITCH  68      // smem row pitch (floats): 64 members + centroid @64, pad

__device__ double g_acc;

__global__ void init_kernel() { g_acc = 0.0; }

__global__ void finalize_kernel(float* out) { out[0] = (float)g_acc; }

// ---------------- cross entropy: one warp per row -------------------------
__global__ void ce_kernel(const float* __restrict__ logits,
                          const int* __restrict__ tgt,
                          int N, int C) {
    int row  = blockIdx.x * (blockDim.x >> 5) + (threadIdx.x >> 5);
    int lane = threadIdx.x & 31;
    if (row >= N) return;
    const float* x = logits + (size_t)row * C;

    float mx = -3.402823466e38f;
    for (int c = lane; c < C; c += 32) mx = fmaxf(mx, x[c]);
    #pragma unroll
    for (int o = 16; o; o >>= 1) mx = fmaxf(mx, __shfl_xor_sync(0xffffffffu, mx, o));

    float s = 0.f;
    for (int c = lane; c < C; c += 32) s += __expf(x[c] - mx);
    #pragma unroll
    for (int o = 16; o; o >>= 1) s += __shfl_xor_sync(0xffffffffu, s, o);

    if (lane == 0) {
        float xt  = x[tgt[row]];
        float nll = -(xt - mx - logf(s));
        atomicAdd(&g_acc, (double)nll / (double)N);
    }
}

// ---------------- group kernel: augmented Gram (64 members + centroid) -----
// One block per group. Shared tile As[kk][col]: cols 0..63 = members,
// col 64 = centroid. 16x16 threads, each owns a 4x4 tile of the 64x64 Gram.
__global__ __launch_bounds__(256)
void group_kernel(const float* __restrict__ train,
                  const float* __restrict__ unl,
                  const int* __restrict__ cids,
                  const int* __restrict__ mids,
                  int C, float inv_align, float inv_rob) {
    __shared__ __align__(16) float As[KTILE][PITCH];   // ~34.8 KB
    __shared__ float sq[KMEM + 1];
    __shared__ float red[64];
    __shared__ int   mrow[KMEM];
    __shared__ int   crow_s;
    __shared__ float redbuf[8];

    const int tid = threadIdx.x;
    const int g   = blockIdx.x;

    if (tid < KMEM) mrow[tid] = mids[g * KMEM + tid];
    if (tid == KMEM) crow_s = cids[g];
    __syncthreads();
    const int crow = crow_s;

    const int tr = tid >> 4;          // 0..15
    const int tc = tid & 15;          // 0..15

    float acc[4][4];
    #pragma unroll
    for (int i = 0; i < 4; i++)
        #pragma unroll
        for (int j = 0; j < 4; j++) acc[i][j] = 0.f;

    float dotc = 0.f;   // tid<64: dot(centroid, member_tid)
    float sqc  = 0.f;   // tid in [64,128): partial ||centroid||^2

    for (int c0 = 0; c0 < C; c0 += KTILE) {
        // ---- load member tile (k-major) ----
        for (int idx = tid; idx < KMEM * KTILE; idx += 256) {
            int r  = idx >> 7;          // member 0..63
            int kk = idx & (KTILE - 1);
            int c  = c0 + kk;
            As[kk][r] = (c < C) ? __ldg(&unl[(size_t)mrow[r] * C + c]) : 0.f;
        }
        // ---- load centroid into col 64 ----
        if (tid < KTILE) {
            int c = c0 + tid;
            As[tid][KMEM] = (c < C) ? __ldg(&train[(size_t)crow * C + c]) : 0.f;
        }
        __syncthreads();

        // ---- 64x64 Gram accumulation ----
        #pragma unroll 8
        for (int kk = 0; kk < KTILE; kk++) {
            float4 a = *reinterpret_cast<const float4*>(&As[kk][4 * tr]);
            float4 b = *reinterpret_cast<const float4*>(&As[kk][4 * tc]);
            acc[0][0] += a.x * b.x; acc[0][1] += a.x * b.y;
            acc[0][2] += a.x * b.z; acc[0][3] += a.x * b.w;
            acc[1][0] += a.y * b.x; acc[1][1] += a.y * b.y;
            acc[1][2] += a.y * b.z; acc[1][3] += a.y * b.w;
            acc[2][0] += a.z * b.x; acc[2][1] += a.z * b.y;
            acc[2][2] += a.z * b.z; acc[2][3] += a.z * b.w;
            acc[3][0] += a.w * b.x; acc[3][1] += a.w * b.y;
            acc[3][2] += a.w * b.z; acc[3][3] += a.w * b.w;
        }

        // ---- centroid dots (warps 0-1) and centroid norm (warps 2-3) ----
        if (tid < KMEM) {
            float d = 0.f;
            #pragma unroll 8
            for (int kk = 0; kk < KTILE; kk++)
                d += As[kk][KMEM] * As[kk][tid];
            dotc += d;
        } else if (tid < 128) {
            float c1 = As[tid - 64][KMEM];
            float c2 = As[tid][KMEM];
            sqc += c1 * c1 + c2 * c2;
        }
        __syncthreads();
    }

    // ---- diagonal -> sq[], centroid norm -> sq[64] ----
    if (tr == tc) {
        #pragma unroll
        for (int i = 0; i < 4; i++) sq[4 * tr + i] = acc[i][i];
    }
    if (tid >= 64 && tid < 128) red[tid - 64] = sqc;
    __syncthreads();
    if (tid == 0) {
        float s = 0.f;
        for (int i = 0; i < 64; i++) s += red[i];
        sq[KMEM] = s;
    }
    __syncthreads();

    // ---- robustness: upper-triangle distances from this thread's 4x4 tile
    float rsum = 0.f;
    const int r0 = 4 * tr, c0v = 4 * tc;
    #pragma unroll
    for (int i = 0; i < 4; i++) {
        #pragma unroll
        for (int j = 0; j < 4; j++) {
            int r = r0 + i, c = c0v + j;
            if (r < c) {
                float d2 = sq[r] + sq[c] - 2.f * acc[i][j];
                rsum += (d2 > 0.f) ? sqrtf(d2) : 0.f;
            }
        }
    }
    // ---- alignment: centroid-member distances
    float asum = 0.f;
    if (tid < KMEM) {
        float d2 = sq[tid] + sq[KMEM] - 2.f * dotc;
        asum = (d2 > 0.f) ? sqrtf(d2) : 0.f;
    }

    float part = LAMBDA_1 * inv_align * asum + LAMBDA_2 * inv_rob * rsum;

    // ---- block reduce ----
    #pragma unroll
    for (int o = 16; o; o >>= 1) part += __shfl_xor_sync(0xffffffffu, part, o);
    if ((tid & 31) == 0) redbuf[tid >> 5] = part;
    __syncthreads();
    if (tid < 8) {
        float v = redbuf[tid];
        #pragma unroll
        for (int o = 4; o; o >>= 1) v += __shfl_xor_sync(0xffu, v, o, 8);
        if (tid == 0) atomicAdd(&g_acc, (double)v);
    }
}

// ---------------------------------------------------------------------------
extern "C" void kernel_launch(void* const* d_in, const int* in_sizes, int n_in,
                              void* d_out, int out_size) {
    const float* train = (const float*)d_in[0];
    const int*   tgt   = (const int*)d_in[1];
    const float* unl   = (const float*)d_in[2];
    const int*   cids  = (const int*)d_in[3];
    const int*   mids  = (const int*)d_in[4];

    int n_train = in_sizes[1];
    int C       = in_sizes[0] / n_train;
    int G       = in_sizes[3];
    int K       = in_sizes[4] / G;          // expected 64
    int n_unl   = in_sizes[2] / C;
    (void)K;

    float inv_align = 1.0f / (float)n_unl;
    float inv_rob   = 1.0f / ((float)K * (float)n_unl);

    init_kernel<<<1, 1>>>();
    ce_kernel<<<(n_train + 7) / 8, 256>>>(train, tgt, n_train, C);
    group_kernel<<<G, 256>>>(train, unl, cids, mids, C, inv_align, inv_rob);
    finalize_kernel<<<1, 1>>>((float*)d_out);
}

// round 4
// speedup vs baseline: 1.7159x; 1.7159x over previous
#include <cuda_runtime.h>
#include <cuda_bf16.h>
#include <cstdint>

// ---------------------------------------------------------------------------
// Loss_46102178955400 — mma.sync (bf16 HMMA) version; tcgen05 unavailable
// because harness PTX targets compute_103 (no 'a' features).
//   ce    = mean NLL over train_logits [4096,1000]
//   align = sum_g sum_k ||centroid_g - member_gk|| / N_unl
//   robust= sum_g sum_{i<j} ||member_gi - member_gj|| / (K*N_unl)
// Group path: 2 groups/CTA. Per group, smem tile X[80][72] bf16 (rows 0-63
// members, 64 centroid, 65-79 zero). D[64x80] = X(0..63) * X^T via
// mma.m16n8k16; diag -> sq, col 64 -> centroid dots.
// ---------------------------------------------------------------------------

#define LAMBDA_1 1.0f
#define LAMBDA_2 0.5f
#define KC     64          // bf16 k-chunk per tile
#define RG     80          // padded rows per group
#define PIT    72          // bf16 row pitch (144 bytes)
#define PITB   144

__device__ double g_acc = 0.0;

struct __align__(16) GS {
    __nv_bfloat16 X[2][RG][PIT];   // 23040 B
    float sq_sh[128];
    float csq[2];
    float red[8];
    int   mrow[128];
    int   crow[2];
};

__device__ __forceinline__ uint32_t smem_u32(const void* p) {
    uint32_t a;
    asm("{ .reg .u64 t; cvta.to.shared.u64 t, %1; cvt.u32.u64 %0, t; }"
        : "=r"(a) : "l"(p));
    return a;
}
__device__ __forceinline__ void ldm_x4(uint32_t a[4], uint32_t addr) {
    asm volatile("ldmatrix.sync.aligned.m8n8.x4.shared.b16 {%0,%1,%2,%3},[%4];"
                 : "=r"(a[0]), "=r"(a[1]), "=r"(a[2]), "=r"(a[3]) : "r"(addr));
}
__device__ __forceinline__ void mma_bf16(float* c, const uint32_t a[4],
                                         uint32_t b0, uint32_t b1) {
    asm volatile("mma.sync.aligned.m16n8k16.row.col.f32.bf16.bf16.f32 "
                 "{%0,%1,%2,%3},{%4,%5,%6,%7},{%8,%9},{%0,%1,%2,%3};"
                 : "+f"(c[0]), "+f"(c[1]), "+f"(c[2]), "+f"(c[3])
                 : "r"(a[0]), "r"(a[1]), "r"(a[2]), "r"(a[3]), "r"(b0), "r"(b1));
}

__global__ __launch_bounds__(256)
void fused_kernel(const float* __restrict__ train,
                  const int* __restrict__ tgt,
                  const float* __restrict__ unl,
                  const int* __restrict__ cids,
                  const int* __restrict__ mids,
                  int C, int G, int n_train,
                  float inv_align, float inv_rob) {
    const int tid  = threadIdx.x;
    const int wid  = tid >> 5;
    const int lane = tid & 31;
    const int nGrp = (G + 1) >> 1;

    // ======================= CE path ======================================
    if ((int)blockIdx.x >= nGrp) {
        int row = ((int)blockIdx.x - nGrp) * 8 + wid;
        if (row >= n_train) return;
        const float* x = train + (size_t)row * C;
        float mx = -3.402823466e38f;
        for (int c = lane; c < C; c += 32) mx = fmaxf(mx, x[c]);
        #pragma unroll
        for (int o = 16; o; o >>= 1) mx = fmaxf(mx, __shfl_xor_sync(~0u, mx, o));
        float s = 0.f;
        for (int c = lane; c < C; c += 32) s += __expf(x[c] - mx);
        #pragma unroll
        for (int o = 16; o; o >>= 1) s += __shfl_xor_sync(~0u, s, o);
        if (lane == 0) {
            float nll = -(x[tgt[row]] - mx - logf(s));
            atomicAdd(&g_acc, (double)nll / (double)n_train);
        }
        return;
    }

    // ======================= group path ===================================
    __shared__ GS s;
    const int g0 = 2 * (int)blockIdx.x;
    int g1 = g0 + 1;
    const float w1 = (g1 < G) ? 1.f : 0.f;
    if (g1 >= G) g1 = g0;

    if (tid < 64)        s.mrow[tid] = mids[g0 * 64 + tid];
    else if (tid < 128)  s.mrow[tid] = mids[g1 * 64 + (tid - 64)];
    if (tid == 128) s.crow[0] = cids[g0];
    if (tid == 129) s.crow[1] = cids[g1];
    if (tid == 130) { s.csq[0] = 0.f; s.csq[1] = 0.f; }

    // zero pad rows 65..79 of both groups (never rewritten)
    for (int i = tid; i < 2 * 15 * (PIT / 2); i += 256) {
        int g   = i / (15 * (PIT / 2));
        int rem = i - g * 15 * (PIT / 2);
        int r   = 65 + rem / (PIT / 2);
        int c   = rem % (PIT / 2);
        ((uint32_t*)&s.X[g][r][0])[c] = 0u;
    }
    __syncthreads();

    const int gsel = wid >> 2;           // group this warp computes
    const int m0   = (wid & 3) * 16;     // warp's row tile
    const uint32_t xbase = smem_u32(&s.X[gsel][0][0]);
    const int q = lane >> 3;
    const uint32_t lmo = (uint32_t)(((lane & 7) + ((q & 1) << 3)) * PITB +
                                    (((q >> 1) << 3) << 1));

    float acc[5][8];
    #pragma unroll
    for (int i = 0; i < 5; i++)
        #pragma unroll
        for (int j = 0; j < 8; j++) acc[i][j] = 0.f;

    float cs0 = 0.f, cs1 = 0.f;   // centroid ||c||^2 partials (rounded bf16)

    const int ntiles = (C + KC - 1) / KC;
    for (int t = 0; t < ntiles; t++) {
        const int c0   = t * KC;
        const int colsC = C - c0;          // remaining cols
        __syncthreads();                   // mma readers done with X

        #pragma unroll
        for (int j = 0; j < 20; j++) {
            int i   = tid + (j << 8);      // 0..5119
            int rfl = i >> 5;              // 0..159
            int kk2 = i & 31;
            int g   = rfl >= RG;
            int rl  = rfl - (g ? RG : 0);
            if (rl > 64) continue;
            const float* src = (rl < 64)
                ? unl   + (size_t)s.mrow[(g << 6) + rl] * C + c0
                : train + (size_t)s.crow[g] * C + c0;
            int cc = kk2 << 1;
            float2 v = make_float2(0.f, 0.f);
            if (cc + 1 < colsC)      v = *(const float2*)(src + cc);
            else if (cc < colsC)     v.x = src[cc];
            __nv_bfloat162 h = __float22bfloat162_rn(v);
            *(uint32_t*)&s.X[g][rl][cc] = *(uint32_t*)&h;
            if (rl == 64) {
                float f0 = __bfloat162float(h.x), f1 = __bfloat162float(h.y);
                float ss = f0 * f0 + f1 * f1;
                if (g) cs1 += ss; else cs0 += ss;
            }
        }
        __syncthreads();

        #pragma unroll
        for (int ks = 0; ks < 4; ks++) {
            uint32_t A[4];
            ldm_x4(A, xbase + (uint32_t)(m0 * PITB + ks * 32) + lmo);
            #pragma unroll
            for (int nc = 0; nc < 5; nc++) {
                uint32_t B[4];
                ldm_x4(B, xbase + (uint32_t)(nc * 16 * PITB + ks * 32) + lmo);
                mma_bf16(&acc[nc][0], A, B[0], B[2]);
                mma_bf16(&acc[nc][4], A, B[1], B[3]);
            }
        }
    }

    // ---- csq reduce (contributions live in warp 0, but reduce all warps) --
    float a0 = cs0, a1 = cs1;
    #pragma unroll
    for (int o = 16; o; o >>= 1) {
        a0 += __shfl_xor_sync(~0u, a0, o);
        a1 += __shfl_xor_sync(~0u, a1, o);
    }
    if (lane == 0 && (a0 != 0.f || a1 != 0.f)) {
        atomicAdd(&s.csq[0], a0);
        atomicAdd(&s.csq[1], a1);
    }

    // ---- diag -> sq_sh ----------------------------------------------------
    const int R0 = m0 + (lane >> 2);
    const int Cb = (lane & 3) << 1;
    #pragma unroll
    for (int nc = 0; nc < 5; nc++)
        #pragma unroll
        for (int h = 0; h < 2; h++)
            #pragma unroll
            for (int qq = 0; qq < 4; qq++) {
                int r = R0 + ((qq >> 1) << 3);
                int c = nc * 16 + h * 8 + Cb + (qq & 1);
                if (r == c) s.sq_sh[(gsel << 6) + r] = acc[nc][h * 4 + qq];
            }
    __syncthreads();

    // ---- distances --------------------------------------------------------
    const float* sq  = &s.sq_sh[gsel << 6];
    const float  csq = s.csq[gsel];
    float rsum = 0.f, asum = 0.f;
    #pragma unroll
    for (int nc = 0; nc < 5; nc++)
        #pragma unroll
        for (int h = 0; h < 2; h++)
            #pragma unroll
            for (int qq = 0; qq < 4; qq++) {
                int r = R0 + ((qq >> 1) << 3);
                int c = nc * 16 + h * 8 + Cb + (qq & 1);
                float v = acc[nc][h * 4 + qq];
                if (c < 64) {
                    if (c > r) {
                        float d2 = sq[r] + sq[c] - 2.f * v;
                        rsum += (d2 > 0.f) ? sqrtf(d2) : 0.f;
                    }
                } else if (c == 64) {
                    float d2 = sq[r] + csq - 2.f * v;
                    asum += (d2 > 0.f) ? sqrtf(d2) : 0.f;
                }
            }

    float w = gsel ? w1 : 1.f;
    float part = w * (LAMBDA_1 * inv_align * asum + LAMBDA_2 * inv_rob * rsum);

    #pragma unroll
    for (int o = 16; o; o >>= 1) part += __shfl_xor_sync(~0u, part, o);
    if (lane == 0) s.red[wid] = part;
    __syncthreads();
    if (tid < 8) {
        float v = s.red[tid];
        #pragma unroll
        for (int o = 4; o; o >>= 1) v += __shfl_xor_sync(0xffu, v, o, 8);
        if (tid == 0) atomicAdd(&g_acc, (double)v);
    }
}

__global__ void finalize_kernel(float* out) {
    out[0] = (float)g_acc;
    g_acc  = 0.0;          // reset for next graph replay (deterministic)
}

// ---------------------------------------------------------------------------
extern "C" void kernel_launch(void* const* d_in, const int* in_sizes, int n_in,
                              void* d_out, int out_size) {
    const float* train = (const float*)d_in[0];
    const int*   tgt   = (const int*)d_in[1];
    const float* unl   = (const float*)d_in[2];
    const int*   cids  = (const int*)d_in[3];
    const int*   mids  = (const int*)d_in[4];

    int n_train = in_sizes[1];
    int C       = in_sizes[0] / n_train;
    int G       = in_sizes[3];
    int K       = in_sizes[4] / G;
    int n_unl   = in_sizes[2] / C;

    float inv_align = 1.0f / (float)n_unl;
    float inv_rob   = 1.0f / ((float)K * (float)n_unl);

    int nGrp = (G + 1) / 2;
    int nCe  = (n_train + 7) / 8;
    fused_kernel<<<nGrp + nCe, 256>>>(train, tgt, unl, cids, mids,
                                      C, G, n_train, inv_align, inv_rob);
    finalize_kernel<<<1, 1>>>((float*)d_out);
}